// round 15
// baseline (speedup 1.0000x reference)
#include <cuda_runtime.h>
#include <cstdint>

// ---------------------------------------------------------------------------
// InstanceAdaptiveKeypointDetector2 — bf16x3 mma.sync backbone + fp32 tail.
// R13 -> R14: splits hoisted across KERNELS. Weights pre-split once; GEMM
// epilogues write activations as split bf16 hi/lo planes (same bytes as
// fp32). Layers 2-4 are pure cp.async pipelines (4 stages, 3 in flight,
// ONE barrier per chunk): no LDG staging, no cvt/sub, no STS in loader.
// Mainloop unchanged: ldmatrix.x4 + HMMA. Arithmetic bit-identical to R13.
// B=8, N=16384, C=256, K=16.  Output = [kp_pos (8,16,3) | y (8,16,256)].
// ---------------------------------------------------------------------------

static constexpr int Bc   = 8;
static constexpr int Nn   = 16384;
static constexpr int Kc   = 16;
static constexpr int Mtot = Bc * Nn;          // 131072
#define EPSBN 1e-5f

// ------------------------------ scratch ------------------------------------
// activation split planes (each plane: M x Kd/2 uint32 words)
__device__ __align__(256) uint32_t g_x1h[(size_t)Mtot * 128];
__device__ __align__(256) uint32_t g_x1l[(size_t)Mtot * 128];
__device__ __align__(256) uint32_t g_x2h[(size_t)Mtot * 128];
__device__ __align__(256) uint32_t g_x2l[(size_t)Mtot * 128];
__device__ __align__(256) uint32_t g_x3h[(size_t)Mtot * 256];
__device__ __align__(256) uint32_t g_x3l[(size_t)Mtot * 256];
// weight split planes
__device__ __align__(256) uint32_t g_w2h[256 * 128];
__device__ __align__(256) uint32_t g_w2l[256 * 128];
__device__ __align__(256) uint32_t g_w3h[512 * 128];
__device__ __align__(256) uint32_t g_w3l[512 * 128];
__device__ __align__(256) uint32_t g_woh[64 * 256];    // padded 48 -> 64 rows
__device__ __align__(256) uint32_t g_wol[64 * 256];
// tail scratch
__device__ __align__(256) float g_off[(size_t)Mtot * 48];
__device__ __align__(256) float g_e[(size_t)Mtot * 16];
__device__ __align__(256) float g_sumxyz[Bc * 3];
__device__ __align__(256) float g_kpp[Bc * Kc * 3];
__device__ __align__(256) float g_spart[Bc * 64 * 16];
__device__ __align__(256) float g_S[Bc * Kc];
__device__ __align__(256) float g_fpart[(size_t)Bc * 4 * 16 * 16 * 64];
__device__ __align__(256) float g_kpf[Bc * Kc * 256];
__device__ __align__(256) float g_y1[Bc * Kc * 256];
__device__ __align__(256) float g_y2[Bc * Kc * 256];

// ------------------------------- helpers -----------------------------------
__device__ __forceinline__ uint32_t smem_u32(const void* p) {
    uint32_t a;
    asm("{ .reg .u64 t; cvta.to.shared.u64 t, %1; cvt.u32.u64 %0, t; }"
        : "=r"(a) : "l"(p));
    return a;
}
__device__ __forceinline__ void cp_async16(uint32_t dst, const void* src) {
    asm volatile("cp.async.cg.shared.global [%0], [%1], 16;" :: "r"(dst), "l"(src));
}
__device__ __forceinline__ void cp_commit() {
    asm volatile("cp.async.commit_group;" ::: "memory");
}
template <int N>
__device__ __forceinline__ void cp_wait() {
    asm volatile("cp.async.wait_group %0;" :: "n"(N) : "memory");
}

// bf16 m16n8k16 mma, fp32 accumulate
__device__ __forceinline__ void mma_bf16(float* c, const uint32_t* a, const uint32_t* b) {
    asm volatile(
        "mma.sync.aligned.m16n8k16.row.col.f32.bf16.bf16.f32 "
        "{%0,%1,%2,%3}, {%4,%5,%6,%7}, {%8,%9}, {%0,%1,%2,%3};"
        : "+f"(c[0]), "+f"(c[1]), "+f"(c[2]), "+f"(c[3])
        : "r"(a[0]), "r"(a[1]), "r"(a[2]), "r"(a[3]), "r"(b[0]), "r"(b[1]));
}
// ldmatrix x4 (non-transposed), b16
__device__ __forceinline__ void ldsm4(uint32_t* r, uint32_t addr) {
    asm volatile("ldmatrix.sync.aligned.m8n8.x4.shared.b16 {%0,%1,%2,%3}, [%4];"
                 : "=r"(r[0]), "=r"(r[1]), "=r"(r[2]), "=r"(r[3]) : "r"(addr));
}
// split consecutive fp32 pair (x = even k, y = odd k) into bf16x2 hi + residual lo
__device__ __forceinline__ void split_bf(float x, float y, uint32_t& hi, uint32_t& lo) {
    asm("cvt.rn.bf16x2.f32 %0, %1, %2;" : "=r"(hi) : "f"(y), "f"(x));
    float h0 = __uint_as_float(hi << 16);
    float h1 = __uint_as_float(hi & 0xFFFF0000u);
    asm("cvt.rn.bf16x2.f32 %0, %1, %2;" : "=r"(lo) : "f"(y - h1), "f"(x - h0));
}

static constexpr int WSTR = 12;      // smem words per 16-K row (8 data + 4 pad)

// -------------------- weight pre-split (once per launch) -------------------
__global__ void presplit_kernel(const float* __restrict__ W, uint32_t* __restrict__ H,
                                uint32_t* __restrict__ L, int Kw, int Dvalid, int total) {
    int idx = blockIdx.x * 256 + threadIdx.x;
    if (idx >= total) return;
    int r = idx / Kw, c = idx % Kw;
    uint32_t hi = 0, lo = 0;
    if (r < Dvalid) {
        const float* p = W + (size_t)r * (Kw * 2) + 2 * c;
        split_bf(p[0], p[1], hi, lo);
    }
    H[idx] = hi; L[idx] = lo;
}

// ---------------- layer-1 GEMM: fp32 loader, split-plane epilogue ----------
// (R13 loader/compute verbatim; epilogue writes bf16 hi/lo planes.)
__global__ __launch_bounds__(256, 2) void l1_gemm(
    const float* __restrict__ A, const float* __restrict__ W,
    const float* __restrict__ P0, const float* __restrict__ P1,
    const float* __restrict__ P2, const float* __restrict__ P3,
    uint32_t* __restrict__ Ch, uint32_t* __restrict__ Cl, int Kd, int D)
{
    constexpr int NT = 128, NTW = 32, NTC = 4, NPAIR = 2, NB4 = 2;
    constexpr int TILE_A = 128 * WSTR, TILE_B = NT * WSTR;
    constexpr int STAGEW = 2 * (TILE_A + TILE_B);

    extern __shared__ __align__(16) uint32_t smw[];
    const uint32_t smb = smem_u32(smw);

    const int tid = threadIdx.x;
    const int wid = tid >> 5, lane = tid & 31;
    const int wm = wid & 1, wn = wid >> 1;
    const int gq = lane >> 2, tq = lane & 3;
    const int m0 = blockIdx.x * 128, d0 = blockIdx.y * NT;

    const int q2 = lane >> 3, rr = lane & 7;
    const uint32_t aOff = (uint32_t)(((wm * 64 + (q2 & 1) * 8 + rr) * WSTR + (q2 >> 1) * 4) * 4);
    const uint32_t bOff = (uint32_t)(((wn * NTW + (q2 >> 1) * 8 + rr) * WSTR + (q2 & 1) * 4) * 4);

    const float* Ap = A + (size_t)m0 * Kd;
    const int nch = Kd / 16;
    const int lr = tid >> 2, lq = tid & 3;

    float4 ra[2], rb[NB4];
    auto ldg = [&](int ch) {
        const int k0 = ch * 16;
#pragma unroll
        for (int i = 0; i < 2; ++i)
            ra[i] = *reinterpret_cast<const float4*>(Ap + (size_t)(lr + i * 64) * Kd + k0 + lq * 4);
#pragma unroll
        for (int i = 0; i < NB4; ++i)
            rb[i] = *reinterpret_cast<const float4*>(W + (size_t)(d0 + lr + i * 64) * Kd + k0 + lq * 4);
    };
    auto sts = [&](int buf) {
        uint32_t* base = smw + buf * STAGEW;
#pragma unroll
        for (int i = 0; i < 2; ++i) {
            uint32_t h0, l0, h1, l1;
            split_bf(ra[i].x, ra[i].y, h0, l0);
            split_bf(ra[i].z, ra[i].w, h1, l1);
            const int r = lr + i * 64;
            *reinterpret_cast<uint2*>(base + r * WSTR + 2 * lq)          = make_uint2(h0, h1);
            *reinterpret_cast<uint2*>(base + TILE_A + r * WSTR + 2 * lq) = make_uint2(l0, l1);
        }
        uint32_t* bb = base + 2 * TILE_A;
#pragma unroll
        for (int i = 0; i < NB4; ++i) {
            uint32_t h0, l0, h1, l1;
            split_bf(rb[i].x, rb[i].y, h0, l0);
            split_bf(rb[i].z, rb[i].w, h1, l1);
            const int r = lr + i * 64;
            *reinterpret_cast<uint2*>(bb + r * WSTR + 2 * lq)          = make_uint2(h0, h1);
            *reinterpret_cast<uint2*>(bb + TILE_B + r * WSTR + 2 * lq) = make_uint2(l0, l1);
        }
    };

    float acc[4][NTC][4];
#pragma unroll
    for (int mt = 0; mt < 4; ++mt)
#pragma unroll
        for (int nt = 0; nt < NTC; ++nt)
#pragma unroll
            for (int q = 0; q < 4; ++q) acc[mt][nt][q] = 0.f;

    ldg(0); sts(0); ldg(1);
    __syncthreads();

    for (int ch = 0; ch < nch; ++ch) {
        {
            const uint32_t sAh = smb + (uint32_t)((ch & 1) * STAGEW) * 4u;
            const uint32_t sAl = sAh + (uint32_t)TILE_A * 4u;
            const uint32_t sBh = sAh + (uint32_t)(2 * TILE_A) * 4u;
            const uint32_t sBl = sBh + (uint32_t)TILE_B * 4u;
            uint32_t bh4[NPAIR][4], bl4[NPAIR][4];
#pragma unroll
            for (int p = 0; p < NPAIR; ++p) {
                const uint32_t po = (uint32_t)(p * 16 * WSTR * 4);
                ldsm4(bh4[p], sBh + bOff + po);
                ldsm4(bl4[p], sBl + bOff + po);
            }
#pragma unroll
            for (int mt = 0; mt < 4; ++mt) {
                const uint32_t mo = (uint32_t)(mt * 16 * WSTR * 4);
                uint32_t ah[4], al[4];
                ldsm4(ah, sAh + aOff + mo);
                ldsm4(al, sAl + aOff + mo);
#pragma unroll
                for (int nt = 0; nt < NTC; ++nt) {
                    const uint32_t* bh = &bh4[nt >> 1][(nt & 1) * 2];
                    const uint32_t* bl = &bl4[nt >> 1][(nt & 1) * 2];
                    mma_bf16(acc[mt][nt], ah, bh);
                    mma_bf16(acc[mt][nt], al, bh);
                    mma_bf16(acc[mt][nt], ah, bl);
                }
            }
        }
        if (ch + 1 < nch) sts((ch + 1) & 1);
        if (ch + 2 < nch) ldg(ch + 2);
        __syncthreads();
    }

    // epilogue: BN+ReLU then split-plane store
    const int Dw = D >> 1;
#pragma unroll
    for (int nt = 0; nt < NTC; ++nt) {
        float sc[2], tt[2];
#pragma unroll
        for (int j = 0; j < 2; ++j) {
            const int d = d0 + wn * NTW + nt * 8 + 2 * tq + j;
            float s = P0[d] * rsqrtf(P3[d] + EPSBN);
            sc[j] = s;
            tt[j] = P1[d] - P2[d] * s;
        }
#pragma unroll
        for (int mt = 0; mt < 4; ++mt) {
            const int m = m0 + wm * 64 + mt * 16 + gq;
            const int d = d0 + wn * NTW + nt * 8 + 2 * tq;
            float v0 = fmaxf(acc[mt][nt][0] * sc[0] + tt[0], 0.f);
            float v1 = fmaxf(acc[mt][nt][1] * sc[1] + tt[1], 0.f);
            float v2 = fmaxf(acc[mt][nt][2] * sc[0] + tt[0], 0.f);
            float v3 = fmaxf(acc[mt][nt][3] * sc[1] + tt[1], 0.f);
            uint32_t h, l;
            split_bf(v0, v1, h, l);
            Ch[(size_t)m * Dw + (d >> 1)] = h;
            Cl[(size_t)m * Dw + (d >> 1)] = l;
            split_bf(v2, v3, h, l);
            Ch[(size_t)(m + 8) * Dw + (d >> 1)] = h;
            Cl[(size_t)(m + 8) * Dw + (d >> 1)] = l;
        }
    }
}

// ---------------- pre-split GEMM: pure cp.async pipeline -------------------
// A,B given as split planes. 4 smem stages, 3 chunks in flight, 1 bar/chunk.
// EPI 0: BN+ReLU -> split-plane store.  EPI 1: +bias -> fp32 store, d<D guard.
template <int EPI, int NT>
__global__ __launch_bounds__(256, 2) void ps_gemm(
    const uint32_t* __restrict__ Ah, const uint32_t* __restrict__ Al,
    const uint32_t* __restrict__ Bh, const uint32_t* __restrict__ Bl,
    const float* __restrict__ P0, const float* __restrict__ P1,
    const float* __restrict__ P2, const float* __restrict__ P3,
    uint32_t* __restrict__ Ch, uint32_t* __restrict__ Cl,
    float* __restrict__ Cf, int Kd, int D)
{
    constexpr int NTW = NT / 4, NTC = NT / 32, NPAIR = NTC / 2;
    constexpr int TILE_A = 128 * WSTR, TILE_B = NT * WSTR;
    constexpr int STAGEW = 2 * (TILE_A + TILE_B);

    extern __shared__ __align__(16) uint32_t smw[];
    const uint32_t smb = smem_u32(smw);

    const int tid = threadIdx.x;
    const int wid = tid >> 5, lane = tid & 31;
    const int wm = wid & 1, wn = wid >> 1;
    const int gq = lane >> 2, tq = lane & 3;
    const int m0 = blockIdx.x * 128, d0 = blockIdx.y * NT;

    const int q2 = lane >> 3, rr = lane & 7;
    const uint32_t aOff = (uint32_t)(((wm * 64 + (q2 & 1) * 8 + rr) * WSTR + (q2 >> 1) * 4) * 4);
    const uint32_t bOff = (uint32_t)(((wn * NTW + (q2 >> 1) * 8 + rr) * WSTR + (q2 & 1) * 4) * 4);

    const int Kw = Kd >> 1;
    const uint32_t* Ahp = Ah + (size_t)m0 * Kw;
    const uint32_t* Alp = Al + (size_t)m0 * Kw;
    const uint32_t* Bhp = Bh + (size_t)d0 * Kw;
    const uint32_t* Blp = Bl + (size_t)d0 * Kw;
    const int nch = Kd / 16;

    // A: per plane, slot = tid -> row tid>>1, half tid&1 (128 rows x 2 halves)
    const int ar = tid >> 1, ahalf = tid & 1;

    auto issue = [&](int ch, int buf) {
        const int koff = ch * 8 + ahalf * 4;
        const uint32_t dA = smb + ((uint32_t)(buf * STAGEW) + (uint32_t)(ar * WSTR + ahalf * 4)) * 4u;
        cp_async16(dA, Ahp + (size_t)ar * Kw + koff);
        cp_async16(dA + (uint32_t)TILE_A * 4u, Alp + (size_t)ar * Kw + koff);
        if (NT == 128) {
            const uint32_t dB = smb + ((uint32_t)(buf * STAGEW + 2 * TILE_A) +
                                       (uint32_t)(ar * WSTR + ahalf * 4)) * 4u;
            cp_async16(dB, Bhp + (size_t)ar * Kw + koff);
            cp_async16(dB + (uint32_t)TILE_B * 4u, Blp + (size_t)ar * Kw + koff);
        } else {   // NT=64: 256 threads cover (2 planes) x (64 rows x 2 halves)
            const int plane = tid >> 7;
            const int s = tid & 127;
            const int br = s >> 1, bhalf = s & 1;
            const int bk = ch * 8 + bhalf * 4;
            const uint32_t dB = smb + ((uint32_t)(buf * STAGEW + 2 * TILE_A + plane * TILE_B) +
                                       (uint32_t)(br * WSTR + bhalf * 4)) * 4u;
            cp_async16(dB, (plane ? Blp : Bhp) + (size_t)br * Kw + bk);
        }
        cp_commit();
    };

    float acc[4][NTC][4];
#pragma unroll
    for (int mt = 0; mt < 4; ++mt)
#pragma unroll
        for (int nt = 0; nt < NTC; ++nt)
#pragma unroll
            for (int q = 0; q < 4; ++q) acc[mt][nt][q] = 0.f;

    issue(0, 0); issue(1, 1); issue(2, 2);

    for (int ch = 0; ch < nch; ++ch) {
        cp_wait<2>();
        __syncthreads();
        {
            const uint32_t sAh = smb + (uint32_t)((ch & 3) * STAGEW) * 4u;
            const uint32_t sAl = sAh + (uint32_t)TILE_A * 4u;
            const uint32_t sBh = sAh + (uint32_t)(2 * TILE_A) * 4u;
            const uint32_t sBl = sBh + (uint32_t)TILE_B * 4u;
            uint32_t bh4[NPAIR][4], bl4[NPAIR][4];
#pragma unroll
            for (int p = 0; p < NPAIR; ++p) {
                const uint32_t po = (uint32_t)(p * 16 * WSTR * 4);
                ldsm4(bh4[p], sBh + bOff + po);
                ldsm4(bl4[p], sBl + bOff + po);
            }
#pragma unroll
            for (int mt = 0; mt < 4; ++mt) {
                const uint32_t mo = (uint32_t)(mt * 16 * WSTR * 4);
                uint32_t ah[4], al[4];
                ldsm4(ah, sAh + aOff + mo);
                ldsm4(al, sAl + aOff + mo);
#pragma unroll
                for (int nt = 0; nt < NTC; ++nt) {
                    const uint32_t* bh = &bh4[nt >> 1][(nt & 1) * 2];
                    const uint32_t* bl = &bl4[nt >> 1][(nt & 1) * 2];
                    mma_bf16(acc[mt][nt], ah, bh);
                    mma_bf16(acc[mt][nt], al, bh);
                    mma_bf16(acc[mt][nt], ah, bl);
                }
            }
        }
        // buffer (ch+3)&3 was consumed at iter ch-1; the barrier above protects it
        if (ch + 3 < nch) issue(ch + 3, (ch + 3) & 3);
        else cp_commit();                      // keep group accounting uniform
    }

    // ------------------------------ epilogue -------------------------------
#pragma unroll
    for (int nt = 0; nt < NTC; ++nt) {
        float sc[2], tt[2];
#pragma unroll
        for (int j = 0; j < 2; ++j) {
            const int d = d0 + wn * NTW + nt * 8 + 2 * tq + j;
            if (EPI == 0) {
                float s = P0[d] * rsqrtf(P3[d] + EPSBN);
                sc[j] = s;
                tt[j] = P1[d] - P2[d] * s;
            } else {
                sc[j] = 1.f;
                tt[j] = (d < D) ? P0[d] : 0.f;
            }
        }
#pragma unroll
        for (int mt = 0; mt < 4; ++mt) {
            const int m = m0 + wm * 64 + mt * 16 + gq;
            const int d = d0 + wn * NTW + nt * 8 + 2 * tq;
            float v0 = acc[mt][nt][0] * sc[0] + tt[0];
            float v1 = acc[mt][nt][1] * sc[1] + tt[1];
            float v2 = acc[mt][nt][2] * sc[0] + tt[0];
            float v3 = acc[mt][nt][3] * sc[1] + tt[1];
            if (EPI == 0) {
                v0 = fmaxf(v0, 0.f); v1 = fmaxf(v1, 0.f);
                v2 = fmaxf(v2, 0.f); v3 = fmaxf(v3, 0.f);
                const int Dw = D >> 1;
                uint32_t h, l;
                split_bf(v0, v1, h, l);
                Ch[(size_t)m * Dw + (d >> 1)] = h;
                Cl[(size_t)m * Dw + (d >> 1)] = l;
                split_bf(v2, v3, h, l);
                Ch[(size_t)(m + 8) * Dw + (d >> 1)] = h;
                Cl[(size_t)(m + 8) * Dw + (d >> 1)] = l;
            } else if (d < D) {
                *reinterpret_cast<float2*>(Cf + (size_t)m * D + d)       = make_float2(v0, v1);
                *reinterpret_cast<float2*>(Cf + (size_t)(m + 8) * D + d) = make_float2(v2, v3);
            }
        }
    }
}

// ------------------------- sum of xyz over points --------------------------
__global__ void sumxyz_kernel(const float* __restrict__ xyz, float* __restrict__ out) {
    const int b = blockIdx.x;
    const int tid = threadIdx.x;
    __shared__ float red[256][4];
    float s0 = 0.f, s1 = 0.f, s2 = 0.f;
    const float* p = xyz + (size_t)b * Nn * 3;
    for (int n = tid; n < Nn; n += 256) {
        s0 += p[n * 3 + 0];
        s1 += p[n * 3 + 1];
        s2 += p[n * 3 + 2];
    }
    red[tid][0] = s0; red[tid][1] = s1; red[tid][2] = s2;
    __syncthreads();
    for (int st = 128; st > 0; st >>= 1) {
        if (tid < st) {
            red[tid][0] += red[tid + st][0];
            red[tid][1] += red[tid + st][1];
            red[tid][2] += red[tid + st][2];
        }
        __syncthreads();
    }
    if (tid < 3) out[b * 3 + tid] = red[0][tid];
}

// ------------------------------ kp_pos -------------------------------------
__global__ void kppos_kernel(const float* __restrict__ off, const float* __restrict__ sxyz,
                             float* __restrict__ kpp, float* __restrict__ outp) {
    const int b = blockIdx.x >> 4;
    const int k = blockIdx.x & 15;
    const int tid = threadIdx.x;
    __shared__ float red[256][4];
    float s0 = 0.f, s1 = 0.f, s2 = 0.f;
    const float* p = off + (size_t)b * Nn * 48 + k * 3;
    for (int n = tid; n < Nn; n += 256) {
        size_t base = (size_t)n * 48;
        s0 += p[base + 0];
        s1 += p[base + 1];
        s2 += p[base + 2];
    }
    red[tid][0] = s0; red[tid][1] = s1; red[tid][2] = s2;
    __syncthreads();
    for (int st = 128; st > 0; st >>= 1) {
        if (tid < st) {
            red[tid][0] += red[tid + st][0];
            red[tid][1] += red[tid + st][1];
            red[tid][2] += red[tid + st][2];
        }
        __syncthreads();
    }
    if (tid < 3) {
        float v = (red[0][tid] + sxyz[b * 3 + tid]) * (1.f / (float)Nn);
        kpp[b * 48 + k * 3 + tid]  = v;
        outp[b * 48 + k * 3 + tid] = v;   // kp_pos is the first output
    }
}

// -------------------- exp(-dist) + per-block partial sums ------------------
__global__ __launch_bounds__(256) void expdist_kernel(
    const float* __restrict__ xyz, const float* __restrict__ off,
    const float* __restrict__ kpp, float* __restrict__ Eo, float* __restrict__ Spart)
{
    const int b = blockIdx.x >> 6;
    const int chunk = blockIdx.x & 63;
    const int tid = threadIdx.x;
    const int n = chunk * 256 + tid;
    const size_t gid = (size_t)b * Nn + n;

    __shared__ float kps[48];
    __shared__ float eS[256][17];
    if (tid < 48) kps[tid] = kpp[b * 48 + tid];
    __syncthreads();

    float4 ob4[12];
    const float4* op = reinterpret_cast<const float4*>(off + gid * 48);
#pragma unroll
    for (int i = 0; i < 12; ++i) ob4[i] = op[i];
    const float* ob = reinterpret_cast<const float*>(ob4);

    const float px = xyz[gid * 3 + 0];
    const float py = xyz[gid * 3 + 1];
    const float pz = xyz[gid * 3 + 2];

    float4 eb4[4];
    float* eb = reinterpret_cast<float*>(eb4);
#pragma unroll
    for (int k = 0; k < 16; ++k) {
        float vx = px + ob[3 * k + 0] - kps[3 * k + 0];
        float vy = py + ob[3 * k + 1] - kps[3 * k + 1];
        float vz = pz + ob[3 * k + 2] - kps[3 * k + 2];
        float e = expf(-sqrtf(vx * vx + vy * vy + vz * vz));
        eb[k] = e;
        eS[tid][k] = e;
    }
    float4* ew = reinterpret_cast<float4*>(Eo + gid * 16);
#pragma unroll
    for (int i = 0; i < 4; ++i) ew[i] = eb4[i];

    __syncthreads();
    for (int st = 128; st > 0; st >>= 1) {
        if (tid < st) {
#pragma unroll
            for (int k = 0; k < 16; ++k) eS[tid][k] += eS[tid + st][k];
        }
        __syncthreads();
    }
    if (tid < 16) Spart[(size_t)(b * 64 + chunk) * 16 + tid] = eS[0][tid];
}

// ------------------------ softmax denominators -----------------------------
__global__ void sreduce_kernel(const float* __restrict__ Spart, float* __restrict__ S) {
    const int t = threadIdx.x;          // 128 threads = (b,k)
    const int b = t >> 4, k = t & 15;
    float s = 0.f;
    for (int c = 0; c < 64; ++c) s += Spart[(size_t)(b * 64 + c) * 16 + k];
    S[t] = s;
}

// ------------------- keypoint feature pooling (partial) --------------------
__global__ __launch_bounds__(256) void kpfeat_partial_kernel(
    const float* __restrict__ F, const float* __restrict__ E, float* __restrict__ P)
{
    const int slab = blockIdx.x;   // 16 slabs of 1024 points
    const int cc   = blockIdx.y;   // 4 chunks of 64 channels
    const int b    = blockIdx.z;
    const int tid  = threadIdx.x;
    const int cl = tid & 63, kg = tid >> 6;

    __shared__ float Fs[16][64];
    __shared__ float es[16][17];
    float a0 = 0.f, a1 = 0.f, a2 = 0.f, a3 = 0.f;
    const int nbase = slab * 1024;

    for (int c0 = 0; c0 < 1024; c0 += 16) {
        __syncthreads();
#pragma unroll
        for (int r = 0; r < 4; ++r) {
            int j = r * 256 + tid;
            int nn = j >> 6, c = j & 63;
            Fs[nn][c] = F[(size_t)(b * Nn + nbase + c0 + nn) * 256 + cc * 64 + c];
        }
        {
            int nn = tid >> 4, kk = tid & 15;
            es[nn][kk] = E[(size_t)(b * Nn + nbase + c0 + nn) * 16 + kk];
        }
        __syncthreads();
#pragma unroll
        for (int nn = 0; nn < 16; ++nn) {
            float f = Fs[nn][cl];
            a0 += f * es[nn][kg * 4 + 0];
            a1 += f * es[nn][kg * 4 + 1];
            a2 += f * es[nn][kg * 4 + 2];
            a3 += f * es[nn][kg * 4 + 3];
        }
    }
    size_t base = ((size_t)(b * 4 + cc) * 16 + slab) * 16 * 64;
    P[base + (size_t)(kg * 4 + 0) * 64 + cl] = a0;
    P[base + (size_t)(kg * 4 + 1) * 64 + cl] = a1;
    P[base + (size_t)(kg * 4 + 2) * 64 + cl] = a2;
    P[base + (size_t)(kg * 4 + 3) * 64 + cl] = a3;
}

__global__ void kpfeat_reduce_kernel(const float* __restrict__ P, const float* __restrict__ S,
                                     float* __restrict__ KF) {
    const int b = blockIdx.x >> 4, k = blockIdx.x & 15;
    const int c = threadIdx.x;
    const int cc = c >> 6, cl = c & 63;
    float s = 0.f;
    for (int slab = 0; slab < 16; ++slab)
        s += P[(((size_t)(b * 4 + cc) * 16 + slab) * 16 + k) * 64 + cl];
    KF[(size_t)(b * 16 + k) * 256 + c] = s / S[b * 16 + k];
}

// ---------------------------- keypoint MLP ---------------------------------
template <int MODE>
__global__ __launch_bounds__(256) void mlp_kernel(
    const float* __restrict__ X, const float* __restrict__ W,
    const float* __restrict__ g, const float* __restrict__ bb,
    const float* __restrict__ mm, const float* __restrict__ vv,
    float* __restrict__ Out)
{
    const int d0 = blockIdx.x * 64;
    const int b  = blockIdx.y;
    const int tid = threadIdx.x;
    const int dl = tid & 63, kq = tid >> 6;

    __shared__ float Xs[16][256];
    __shared__ float Ws[64][65];

#pragma unroll
    for (int r = 0; r < 16; ++r) {
        int j = r * 256 + tid;
        (&Xs[0][0])[j] = X[(size_t)b * 16 * 256 + j];
    }

    float acc[4] = {0.f, 0.f, 0.f, 0.f};
    for (int c0 = 0; c0 < 256; c0 += 64) {
        __syncthreads();
#pragma unroll
        for (int r = 0; r < 16; ++r) {
            int j = r * 256 + tid;
            int dr = j >> 6, ccol = j & 63;
            Ws[dr][ccol] = W[(size_t)(d0 + dr) * 256 + c0 + ccol];
        }
        __syncthreads();
#pragma unroll 16
        for (int c = 0; c < 64; ++c) {
            float w = Ws[dl][c];
            acc[0] += Xs[kq + 0][c0 + c] * w;
            acc[1] += Xs[kq + 4][c0 + c] * w;
            acc[2] += Xs[kq + 8][c0 + c] * w;
            acc[3] += Xs[kq + 12][c0 + c] * w;
        }
    }

    const int d = d0 + dl;
    float s = 1.f, t = 0.f;
    if (MODE == 0) {
        s = g[d] * rsqrtf(vv[d] + EPSBN);
        t = bb[d] - mm[d] * s;
    }
#pragma unroll
    for (int r = 0; r < 4; ++r) {
        int k = kq + r * 4;
        float o = (MODE == 0) ? fmaxf(acc[r] * s + t, 0.f) : acc[r];
        Out[(size_t)(b * 16 + k) * 256 + d] = o;
    }
}

// ------------------------------ launcher -----------------------------------
extern "C" void kernel_launch(void* const* d_in, const int* in_sizes, int n_in,
                              void* d_out, int out_size) {
    const float* F   = (const float*)d_in[0];
    const float* xyz = (const float*)d_in[1];
    const float* W1  = (const float*)d_in[2];
    const float* g1  = (const float*)d_in[3];
    const float* b1  = (const float*)d_in[4];
    const float* m1  = (const float*)d_in[5];
    const float* v1  = (const float*)d_in[6];
    const float* W2  = (const float*)d_in[7];
    const float* g2  = (const float*)d_in[8];
    const float* b2  = (const float*)d_in[9];
    const float* m2  = (const float*)d_in[10];
    const float* v2  = (const float*)d_in[11];
    const float* W3  = (const float*)d_in[12];
    const float* g3  = (const float*)d_in[13];
    const float* b3  = (const float*)d_in[14];
    const float* m3  = (const float*)d_in[15];
    const float* v3  = (const float*)d_in[16];
    const float* Wo  = (const float*)d_in[17];
    const float* bo  = (const float*)d_in[18];
    const float* Wm1 = (const float*)d_in[19];
    const float* gm1 = (const float*)d_in[20];
    const float* bm1 = (const float*)d_in[21];
    const float* mm1 = (const float*)d_in[22];
    const float* vm1 = (const float*)d_in[23];
    const float* Wm2 = (const float*)d_in[24];
    const float* gm2 = (const float*)d_in[25];
    const float* bm2 = (const float*)d_in[26];
    const float* mm2 = (const float*)d_in[27];
    const float* vm2 = (const float*)d_in[28];
    const float* Wm3 = (const float*)d_in[29];
    float* out = (float*)d_out;

    uint32_t *x1h, *x1l, *x2h, *x2l, *x3h, *x3l;
    uint32_t *w2h, *w2l, *w3h, *w3l, *woh, *wol;
    float *off, *e, *sxyz, *kpp, *spart, *S, *fpart, *kpf, *y1, *y2;
    cudaGetSymbolAddress((void**)&x1h, g_x1h);  cudaGetSymbolAddress((void**)&x1l, g_x1l);
    cudaGetSymbolAddress((void**)&x2h, g_x2h);  cudaGetSymbolAddress((void**)&x2l, g_x2l);
    cudaGetSymbolAddress((void**)&x3h, g_x3h);  cudaGetSymbolAddress((void**)&x3l, g_x3l);
    cudaGetSymbolAddress((void**)&w2h, g_w2h);  cudaGetSymbolAddress((void**)&w2l, g_w2l);
    cudaGetSymbolAddress((void**)&w3h, g_w3h);  cudaGetSymbolAddress((void**)&w3l, g_w3l);
    cudaGetSymbolAddress((void**)&woh, g_woh);  cudaGetSymbolAddress((void**)&wol, g_wol);
    cudaGetSymbolAddress((void**)&off, g_off);
    cudaGetSymbolAddress((void**)&e, g_e);
    cudaGetSymbolAddress((void**)&sxyz, g_sumxyz);
    cudaGetSymbolAddress((void**)&kpp, g_kpp);
    cudaGetSymbolAddress((void**)&spart, g_spart);
    cudaGetSymbolAddress((void**)&S, g_S);
    cudaGetSymbolAddress((void**)&fpart, g_fpart);
    cudaGetSymbolAddress((void**)&kpf, g_kpf);
    cudaGetSymbolAddress((void**)&y1, g_y1);
    cudaGetSymbolAddress((void**)&y2, g_y2);

    constexpr int SM_L1  = 2 * 2 * (128 + 128) * WSTR * 4;   // 49152 B (2 stages)
    constexpr int SM_PS128 = 4 * 2 * (128 + 128) * WSTR * 4; // 98304 B (4 stages)
    constexpr int SM_PS64  = 4 * 2 * (128 + 64)  * WSTR * 4; // 73728 B

    cudaFuncSetAttribute(l1_gemm, cudaFuncAttributeMaxDynamicSharedMemorySize, SM_L1);
    cudaFuncSetAttribute(ps_gemm<0, 128>, cudaFuncAttributeMaxDynamicSharedMemorySize, SM_PS128);
    cudaFuncSetAttribute(ps_gemm<1, 64>,  cudaFuncAttributeMaxDynamicSharedMemorySize, SM_PS64);

    // weight pre-split (Wo zero-padded to 64 rows)
    presplit_kernel<<<(256 * 128 + 255) / 256, 256>>>(W2, w2h, w2l, 128, 256, 256 * 128);
    presplit_kernel<<<(512 * 128 + 255) / 256, 256>>>(W3, w3h, w3l, 128, 512, 512 * 128);
    presplit_kernel<<<(64 * 256 + 255) / 256, 256>>>(Wo, woh, wol, 256, 48, 64 * 256);

    // backbone chain
    l1_gemm<<<dim3(Mtot / 128, 2), 256, SM_L1>>>(F, W1, g1, b1, m1, v1, x1h, x1l, 256, 256);
    ps_gemm<0, 128><<<dim3(Mtot / 128, 2), 256, SM_PS128>>>(x1h, x1l, w2h, w2l,
        g2, b2, m2, v2, x2h, x2l, nullptr, 256, 256);
    ps_gemm<0, 128><<<dim3(Mtot / 128, 4), 256, SM_PS128>>>(x2h, x2l, w3h, w3l,
        g3, b3, m3, v3, x3h, x3l, nullptr, 256, 512);
    ps_gemm<1, 64><<<dim3(Mtot / 128, 1), 256, SM_PS64>>>(x3h, x3l, woh, wol,
        bo, nullptr, nullptr, nullptr, nullptr, nullptr, off, 512, 48);

    // keypoint positions (deterministic mean)
    sumxyz_kernel<<<Bc, 256>>>(xyz, sxyz);
    kppos_kernel<<<Bc * Kc, 256>>>(off, sxyz, kpp, out);
    // softmax weights
    expdist_kernel<<<Bc * 64, 256>>>(xyz, off, kpp, e, spart);
    sreduce_kernel<<<1, 128>>>(spart, S);
    // weighted feature pooling
    kpfeat_partial_kernel<<<dim3(16, 4, Bc), 256>>>(F, e, fpart);
    kpfeat_reduce_kernel<<<Bc * Kc, 256>>>(fpart, S, kpf);
    // keypoint MLP (fp32 — tiny)
    mlp_kernel<0><<<dim3(4, Bc), 256>>>(kpf, Wm1, gm1, bm1, mm1, vm1, y1);
    mlp_kernel<0><<<dim3(4, Bc), 256>>>(y1, Wm2, gm2, bm2, mm2, vm2, y2);
    mlp_kernel<1><<<dim3(4, Bc), 256>>>(y2, Wm3, nullptr, nullptr, nullptr, nullptr,
                                        out + Bc * Kc * 3);
}

// round 17
// speedup vs baseline: 1.1477x; 1.1477x over previous
#include <cuda_runtime.h>
#include <cstdint>

// ---------------------------------------------------------------------------
// InstanceAdaptiveKeypointDetector2 — bf16x3 mma.sync backbone + fp32 tail.
// R13 -> R16: REVERT of R14's split-plane scheme (regressed). Single change
// vs R13: warp tile 64x32 -> 64x64 with 4-warp (128-thread) CTAs. LDSM bytes
// per output fall 1.5x (A fragments fetched 2x not 4x); l1tex (the measured
// 74% bound) per chunk: 80KB -> 64KB. Arithmetic bit-identical to R13.
// B=8, N=16384, C=256, K=16.  Output = [kp_pos (8,16,3) | y (8,16,256)].
// ---------------------------------------------------------------------------

static constexpr int Bc   = 8;
static constexpr int Nn   = 16384;
static constexpr int Kc   = 16;
static constexpr int Mtot = Bc * Nn;          // 131072
#define EPSBN 1e-5f

// ------------------------------ scratch ------------------------------------
__device__ __align__(256) float g_x1[(size_t)Mtot * 256];
__device__ __align__(256) float g_x2[(size_t)Mtot * 256];
__device__ __align__(256) float g_x3[(size_t)Mtot * 512];
__device__ __align__(256) float g_off[(size_t)Mtot * 48];
__device__ __align__(256) float g_e[(size_t)Mtot * 16];
__device__ __align__(256) float g_sumxyz[Bc * 3];
__device__ __align__(256) float g_kpp[Bc * Kc * 3];
__device__ __align__(256) float g_spart[Bc * 64 * 16];
__device__ __align__(256) float g_S[Bc * Kc];
__device__ __align__(256) float g_fpart[(size_t)Bc * 4 * 16 * 16 * 64];
__device__ __align__(256) float g_kpf[Bc * Kc * 256];
__device__ __align__(256) float g_y1[Bc * Kc * 256];
__device__ __align__(256) float g_y2[Bc * Kc * 256];

// ------------------------------- helpers -----------------------------------
__device__ __forceinline__ uint32_t smem_u32(const void* p) {
    uint32_t a;
    asm("{ .reg .u64 t; cvta.to.shared.u64 t, %1; cvt.u32.u64 %0, t; }"
        : "=r"(a) : "l"(p));
    return a;
}
// bf16 m16n8k16 mma, fp32 accumulate
__device__ __forceinline__ void mma_bf16(float* c, const uint32_t* a, const uint32_t* b) {
    asm volatile(
        "mma.sync.aligned.m16n8k16.row.col.f32.bf16.bf16.f32 "
        "{%0,%1,%2,%3}, {%4,%5,%6,%7}, {%8,%9}, {%0,%1,%2,%3};"
        : "+f"(c[0]), "+f"(c[1]), "+f"(c[2]), "+f"(c[3])
        : "r"(a[0]), "r"(a[1]), "r"(a[2]), "r"(a[3]), "r"(b[0]), "r"(b[1]));
}
// ldmatrix x4 (non-transposed), b16
__device__ __forceinline__ void ldsm4(uint32_t* r, uint32_t addr) {
    asm volatile("ldmatrix.sync.aligned.m8n8.x4.shared.b16 {%0,%1,%2,%3}, [%4];"
                 : "=r"(r[0]), "=r"(r[1]), "=r"(r[2]), "=r"(r[3]) : "r"(addr));
}
// split consecutive fp32 pair (x = even k, y = odd k) into bf16x2 hi + residual lo
__device__ __forceinline__ void split_bf(float x, float y, uint32_t& hi, uint32_t& lo) {
    asm("cvt.rn.bf16x2.f32 %0, %1, %2;" : "=r"(hi) : "f"(y), "f"(x));
    float h0 = __uint_as_float(hi << 16);
    float h1 = __uint_as_float(hi & 0xFFFF0000u);
    asm("cvt.rn.bf16x2.f32 %0, %1, %2;" : "=r"(lo) : "f"(y - h1), "f"(x - h0));
}

// ----------------------- bf16x3 tensor-core GEMM ---------------------------
// C[m][d] = epilogue( sum_k A[m][k] * W[d][k] )
// Block tile 128 x NT, chunk = 16 K, 4 warps (2 x 2), warp tile 64 x NT/2.
// smem stage: [Ahi | Alo | Bhi | Blo]; bf16x2 words, row = 8 data words + 4
// pad -> stride 12: LDSM 8-row groups conflict-free.
// MODE 0: relu(z*sc + tt), BN folded.  MODE 1: z + bias, d<D guards.
static constexpr int WSTR = 12;                  // words per 16-K row

template <int MODE, int NT>
__global__ __launch_bounds__(128, 2) void mma_gemm(
    const float* __restrict__ A, const float* __restrict__ W,
    const float* __restrict__ P0, const float* __restrict__ P1,
    const float* __restrict__ P2, const float* __restrict__ P3,
    float* __restrict__ C, int M, int Kd, int D)
{
    constexpr int NTW    = NT / 2;               // warp n-tile (64 or 32)
    constexpr int NTC    = NTW / 8;              // 8-wide nt iterations
    constexpr int NPAIR  = NTC / 2;              // ldmatrix B pair groups
    constexpr int NB4    = NT / 32;              // B float4 loads per thread
    constexpr int TILE_A = 128 * WSTR;           // words
    constexpr int TILE_B = NT * WSTR;
    constexpr int STAGEW = 2 * (TILE_A + TILE_B);

    extern __shared__ __align__(16) uint32_t smw[];
    const uint32_t smb = smem_u32(smw);

    const int tid  = threadIdx.x;
    const int wid  = tid >> 5, lane = tid & 31;
    const int wm   = wid & 1;          // 2 warp rows
    const int wn   = wid >> 1;         // 2 warp cols
    const int gq   = lane >> 2;        // group id 0..7
    const int tq   = lane & 3;         // thread-in-group 0..3
    const int m0   = blockIdx.x * 128;
    const int d0   = blockIdx.y * NT;

    // per-lane ldmatrix address offsets (bytes)
    const int q2 = lane >> 3, rr = lane & 7;
    const uint32_t aOff = (uint32_t)(((wm * 64 + (q2 & 1) * 8 + rr) * WSTR + (q2 >> 1) * 4) * 4);
    const uint32_t bOff = (uint32_t)(((wn * NTW + (q2 >> 1) * 8 + rr) * WSTR + (q2 & 1) * 4) * 4);

    const float* Ap = A + (size_t)m0 * Kd;
    const int nch = Kd / 16;

    // loader mapping: 128 threads; rows lr + i*32, 4 float4 per 16-K row
    const int lr = tid >> 2, lq = tid & 3;

    float4 ra[4], rb[NB4];
    auto ldg = [&](int ch) {
        const int k0 = ch * 16;
#pragma unroll
        for (int i = 0; i < 4; ++i)
            ra[i] = *reinterpret_cast<const float4*>(Ap + (size_t)(lr + i * 32) * Kd + k0 + lq * 4);
#pragma unroll
        for (int i = 0; i < NB4; ++i) {
            const int row = d0 + lr + i * 32;
            if (MODE == 0 || row < D)
                rb[i] = *reinterpret_cast<const float4*>(W + (size_t)row * Kd + k0 + lq * 4);
            else
                rb[i] = make_float4(0.f, 0.f, 0.f, 0.f);
        }
    };
    auto sts = [&](int buf) {
        uint32_t* base = smw + buf * STAGEW;
#pragma unroll
        for (int i = 0; i < 4; ++i) {
            uint32_t h0, l0, h1, l1;
            split_bf(ra[i].x, ra[i].y, h0, l0);
            split_bf(ra[i].z, ra[i].w, h1, l1);
            const int r = lr + i * 32;
            *reinterpret_cast<uint2*>(base + r * WSTR + 2 * lq)          = make_uint2(h0, h1);
            *reinterpret_cast<uint2*>(base + TILE_A + r * WSTR + 2 * lq) = make_uint2(l0, l1);
        }
        uint32_t* bb = base + 2 * TILE_A;
#pragma unroll
        for (int i = 0; i < NB4; ++i) {
            uint32_t h0, l0, h1, l1;
            split_bf(rb[i].x, rb[i].y, h0, l0);
            split_bf(rb[i].z, rb[i].w, h1, l1);
            const int r = lr + i * 32;
            *reinterpret_cast<uint2*>(bb + r * WSTR + 2 * lq)          = make_uint2(h0, h1);
            *reinterpret_cast<uint2*>(bb + TILE_B + r * WSTR + 2 * lq) = make_uint2(l0, l1);
        }
    };

    float acc[4][NTC][4];
#pragma unroll
    for (int mt = 0; mt < 4; ++mt)
#pragma unroll
        for (int nt = 0; nt < NTC; ++nt)
#pragma unroll
            for (int q = 0; q < 4; ++q) acc[mt][nt][q] = 0.f;

    ldg(0); sts(0); ldg(1);
    __syncthreads();

    for (int ch = 0; ch < nch; ++ch) {
        // ---------------- compute chunk ch (LDSM + HMMA only) --------------
        {
            const uint32_t sAh = smb + (uint32_t)((ch & 1) * STAGEW) * 4u;
            const uint32_t sAl = sAh + (uint32_t)TILE_A * 4u;
            const uint32_t sBh = sAh + (uint32_t)(2 * TILE_A) * 4u;
            const uint32_t sBl = sBh + (uint32_t)TILE_B * 4u;

            uint32_t bh4[NPAIR][4], bl4[NPAIR][4];
#pragma unroll
            for (int p = 0; p < NPAIR; ++p) {
                const uint32_t po = (uint32_t)(p * 16 * WSTR * 4);
                ldsm4(bh4[p], sBh + bOff + po);
                ldsm4(bl4[p], sBl + bOff + po);
            }
#pragma unroll
            for (int mt = 0; mt < 4; ++mt) {
                const uint32_t mo = (uint32_t)(mt * 16 * WSTR * 4);
                uint32_t ah[4], al[4];
                ldsm4(ah, sAh + aOff + mo);
                ldsm4(al, sAl + aOff + mo);
#pragma unroll
                for (int nt = 0; nt < NTC; ++nt) {
                    const uint32_t* bh = &bh4[nt >> 1][(nt & 1) * 2];
                    const uint32_t* bl = &bl4[nt >> 1][(nt & 1) * 2];
                    mma_bf16(acc[mt][nt], ah, bh);   // main
                    mma_bf16(acc[mt][nt], al, bh);   // A residual
                    mma_bf16(acc[mt][nt], ah, bl);   // B residual
                }
            }
        }
        // ------------- stage ch+1 into smem, prefetch ch+2 -----------------
        if (ch + 1 < nch) sts((ch + 1) & 1);
        if (ch + 2 < nch) ldg(ch + 2);
        __syncthreads();
    }

    // ------------------------------ epilogue -------------------------------
#pragma unroll
    for (int nt = 0; nt < NTC; ++nt) {
        float sc[2], tt[2];
#pragma unroll
        for (int j = 0; j < 2; ++j) {
            const int d = d0 + wn * NTW + nt * 8 + 2 * tq + j;
            if (MODE == 0) {
                float s = P0[d] * rsqrtf(P3[d] + EPSBN);
                sc[j] = s;
                tt[j] = P1[d] - P2[d] * s;
            } else {
                sc[j] = 1.f;
                tt[j] = (d < D) ? P0[d] : 0.f;
            }
        }
#pragma unroll
        for (int mt = 0; mt < 4; ++mt) {
            const int m = m0 + wm * 64 + mt * 16 + gq;
            const int d = d0 + wn * NTW + nt * 8 + 2 * tq;
            float v0 = acc[mt][nt][0] * sc[0] + tt[0];
            float v1 = acc[mt][nt][1] * sc[1] + tt[1];
            float v2 = acc[mt][nt][2] * sc[0] + tt[0];
            float v3 = acc[mt][nt][3] * sc[1] + tt[1];
            if (MODE == 0) {
                v0 = fmaxf(v0, 0.f); v1 = fmaxf(v1, 0.f);
                v2 = fmaxf(v2, 0.f); v3 = fmaxf(v3, 0.f);
            }
            if (MODE == 0 || d < D) {
                *reinterpret_cast<float2*>(C + (size_t)m * D + d)       = make_float2(v0, v1);
                *reinterpret_cast<float2*>(C + (size_t)(m + 8) * D + d) = make_float2(v2, v3);
            }
        }
    }
}

// ------------------------- sum of xyz over points --------------------------
__global__ void sumxyz_kernel(const float* __restrict__ xyz, float* __restrict__ out) {
    const int b = blockIdx.x;
    const int tid = threadIdx.x;
    __shared__ float red[256][4];
    float s0 = 0.f, s1 = 0.f, s2 = 0.f;
    const float* p = xyz + (size_t)b * Nn * 3;
    for (int n = tid; n < Nn; n += 256) {
        s0 += p[n * 3 + 0];
        s1 += p[n * 3 + 1];
        s2 += p[n * 3 + 2];
    }
    red[tid][0] = s0; red[tid][1] = s1; red[tid][2] = s2;
    __syncthreads();
    for (int st = 128; st > 0; st >>= 1) {
        if (tid < st) {
            red[tid][0] += red[tid + st][0];
            red[tid][1] += red[tid + st][1];
            red[tid][2] += red[tid + st][2];
        }
        __syncthreads();
    }
    if (tid < 3) out[b * 3 + tid] = red[0][tid];
}

// ------------------------------ kp_pos -------------------------------------
__global__ void kppos_kernel(const float* __restrict__ off, const float* __restrict__ sxyz,
                             float* __restrict__ kpp, float* __restrict__ outp) {
    const int b = blockIdx.x >> 4;
    const int k = blockIdx.x & 15;
    const int tid = threadIdx.x;
    __shared__ float red[256][4];
    float s0 = 0.f, s1 = 0.f, s2 = 0.f;
    const float* p = off + (size_t)b * Nn * 48 + k * 3;
    for (int n = tid; n < Nn; n += 256) {
        size_t base = (size_t)n * 48;
        s0 += p[base + 0];
        s1 += p[base + 1];
        s2 += p[base + 2];
    }
    red[tid][0] = s0; red[tid][1] = s1; red[tid][2] = s2;
    __syncthreads();
    for (int st = 128; st > 0; st >>= 1) {
        if (tid < st) {
            red[tid][0] += red[tid + st][0];
            red[tid][1] += red[tid + st][1];
            red[tid][2] += red[tid + st][2];
        }
        __syncthreads();
    }
    if (tid < 3) {
        float v = (red[0][tid] + sxyz[b * 3 + tid]) * (1.f / (float)Nn);
        kpp[b * 48 + k * 3 + tid]  = v;
        outp[b * 48 + k * 3 + tid] = v;   // kp_pos is the first output
    }
}

// -------------------- exp(-dist) + per-block partial sums ------------------
__global__ __launch_bounds__(256) void expdist_kernel(
    const float* __restrict__ xyz, const float* __restrict__ off,
    const float* __restrict__ kpp, float* __restrict__ Eo, float* __restrict__ Spart)
{
    const int b = blockIdx.x >> 6;
    const int chunk = blockIdx.x & 63;
    const int tid = threadIdx.x;
    const int n = chunk * 256 + tid;
    const size_t gid = (size_t)b * Nn + n;

    __shared__ float kps[48];
    __shared__ float eS[256][17];
    if (tid < 48) kps[tid] = kpp[b * 48 + tid];
    __syncthreads();

    float4 ob4[12];
    const float4* op = reinterpret_cast<const float4*>(off + gid * 48);
#pragma unroll
    for (int i = 0; i < 12; ++i) ob4[i] = op[i];
    const float* ob = reinterpret_cast<const float*>(ob4);

    const float px = xyz[gid * 3 + 0];
    const float py = xyz[gid * 3 + 1];
    const float pz = xyz[gid * 3 + 2];

    float4 eb4[4];
    float* eb = reinterpret_cast<float*>(eb4);
#pragma unroll
    for (int k = 0; k < 16; ++k) {
        float vx = px + ob[3 * k + 0] - kps[3 * k + 0];
        float vy = py + ob[3 * k + 1] - kps[3 * k + 1];
        float vz = pz + ob[3 * k + 2] - kps[3 * k + 2];
        float e = expf(-sqrtf(vx * vx + vy * vy + vz * vz));
        eb[k] = e;
        eS[tid][k] = e;
    }
    float4* ew = reinterpret_cast<float4*>(Eo + gid * 16);
#pragma unroll
    for (int i = 0; i < 4; ++i) ew[i] = eb4[i];

    __syncthreads();
    for (int st = 128; st > 0; st >>= 1) {
        if (tid < st) {
#pragma unroll
            for (int k = 0; k < 16; ++k) eS[tid][k] += eS[tid + st][k];
        }
        __syncthreads();
    }
    if (tid < 16) Spart[(size_t)(b * 64 + chunk) * 16 + tid] = eS[0][tid];
}

// ------------------------ softmax denominators -----------------------------
__global__ void sreduce_kernel(const float* __restrict__ Spart, float* __restrict__ S) {
    const int t = threadIdx.x;          // 128 threads = (b,k)
    const int b = t >> 4, k = t & 15;
    float s = 0.f;
    for (int c = 0; c < 64; ++c) s += Spart[(size_t)(b * 64 + c) * 16 + k];
    S[t] = s;
}

// ------------------- keypoint feature pooling (partial) --------------------
__global__ __launch_bounds__(256) void kpfeat_partial_kernel(
    const float* __restrict__ F, const float* __restrict__ E, float* __restrict__ P)
{
    const int slab = blockIdx.x;   // 16 slabs of 1024 points
    const int cc   = blockIdx.y;   // 4 chunks of 64 channels
    const int b    = blockIdx.z;
    const int tid  = threadIdx.x;
    const int cl = tid & 63, kg = tid >> 6;

    __shared__ float Fs[16][64];
    __shared__ float es[16][17];
    float a0 = 0.f, a1 = 0.f, a2 = 0.f, a3 = 0.f;
    const int nbase = slab * 1024;

    for (int c0 = 0; c0 < 1024; c0 += 16) {
        __syncthreads();
#pragma unroll
        for (int r = 0; r < 4; ++r) {
            int j = r * 256 + tid;
            int nn = j >> 6, c = j & 63;
            Fs[nn][c] = F[(size_t)(b * Nn + nbase + c0 + nn) * 256 + cc * 64 + c];
        }
        {
            int nn = tid >> 4, kk = tid & 15;
            es[nn][kk] = E[(size_t)(b * Nn + nbase + c0 + nn) * 16 + kk];
        }
        __syncthreads();
#pragma unroll
        for (int nn = 0; nn < 16; ++nn) {
            float f = Fs[nn][cl];
            a0 += f * es[nn][kg * 4 + 0];
            a1 += f * es[nn][kg * 4 + 1];
            a2 += f * es[nn][kg * 4 + 2];
            a3 += f * es[nn][kg * 4 + 3];
        }
    }
    size_t base = ((size_t)(b * 4 + cc) * 16 + slab) * 16 * 64;
    P[base + (size_t)(kg * 4 + 0) * 64 + cl] = a0;
    P[base + (size_t)(kg * 4 + 1) * 64 + cl] = a1;
    P[base + (size_t)(kg * 4 + 2) * 64 + cl] = a2;
    P[base + (size_t)(kg * 4 + 3) * 64 + cl] = a3;
}

__global__ void kpfeat_reduce_kernel(const float* __restrict__ P, const float* __restrict__ S,
                                     float* __restrict__ KF) {
    const int b = blockIdx.x >> 4, k = blockIdx.x & 15;
    const int c = threadIdx.x;
    const int cc = c >> 6, cl = c & 63;
    float s = 0.f;
    for (int slab = 0; slab < 16; ++slab)
        s += P[(((size_t)(b * 4 + cc) * 16 + slab) * 16 + k) * 64 + cl];
    KF[(size_t)(b * 16 + k) * 256 + c] = s / S[b * 16 + k];
}

// ---------------------------- keypoint MLP ---------------------------------
// MODE 0: relu(bn(X @ W^T)).  MODE 1: plain X @ W^T (no bias).
template <int MODE>
__global__ __launch_bounds__(256) void mlp_kernel(
    const float* __restrict__ X, const float* __restrict__ W,
    const float* __restrict__ g, const float* __restrict__ bb,
    const float* __restrict__ mm, const float* __restrict__ vv,
    float* __restrict__ Out)
{
    const int d0 = blockIdx.x * 64;
    const int b  = blockIdx.y;
    const int tid = threadIdx.x;
    const int dl = tid & 63, kq = tid >> 6;

    __shared__ float Xs[16][256];
    __shared__ float Ws[64][65];

#pragma unroll
    for (int r = 0; r < 16; ++r) {
        int j = r * 256 + tid;
        (&Xs[0][0])[j] = X[(size_t)b * 16 * 256 + j];
    }

    float acc[4] = {0.f, 0.f, 0.f, 0.f};
    for (int c0 = 0; c0 < 256; c0 += 64) {
        __syncthreads();
#pragma unroll
        for (int r = 0; r < 16; ++r) {
            int j = r * 256 + tid;
            int dr = j >> 6, ccol = j & 63;
            Ws[dr][ccol] = W[(size_t)(d0 + dr) * 256 + c0 + ccol];
        }
        __syncthreads();
#pragma unroll 16
        for (int c = 0; c < 64; ++c) {
            float w = Ws[dl][c];
            acc[0] += Xs[kq + 0][c0 + c] * w;
            acc[1] += Xs[kq + 4][c0 + c] * w;
            acc[2] += Xs[kq + 8][c0 + c] * w;
            acc[3] += Xs[kq + 12][c0 + c] * w;
        }
    }

    const int d = d0 + dl;
    float s = 1.f, t = 0.f;
    if (MODE == 0) {
        s = g[d] * rsqrtf(vv[d] + EPSBN);
        t = bb[d] - mm[d] * s;
    }
#pragma unroll
    for (int r = 0; r < 4; ++r) {
        int k = kq + r * 4;
        float o = (MODE == 0) ? fmaxf(acc[r] * s + t, 0.f) : acc[r];
        Out[(size_t)(b * 16 + k) * 256 + d] = o;
    }
}

// ------------------------------ launcher -----------------------------------
extern "C" void kernel_launch(void* const* d_in, const int* in_sizes, int n_in,
                              void* d_out, int out_size) {
    const float* F   = (const float*)d_in[0];
    const float* xyz = (const float*)d_in[1];
    const float* W1  = (const float*)d_in[2];
    const float* g1  = (const float*)d_in[3];
    const float* b1  = (const float*)d_in[4];
    const float* m1  = (const float*)d_in[5];
    const float* v1  = (const float*)d_in[6];
    const float* W2  = (const float*)d_in[7];
    const float* g2  = (const float*)d_in[8];
    const float* b2  = (const float*)d_in[9];
    const float* m2  = (const float*)d_in[10];
    const float* v2  = (const float*)d_in[11];
    const float* W3  = (const float*)d_in[12];
    const float* g3  = (const float*)d_in[13];
    const float* b3  = (const float*)d_in[14];
    const float* m3  = (const float*)d_in[15];
    const float* v3  = (const float*)d_in[16];
    const float* Wo  = (const float*)d_in[17];
    const float* bo  = (const float*)d_in[18];
    const float* Wm1 = (const float*)d_in[19];
    const float* gm1 = (const float*)d_in[20];
    const float* bm1 = (const float*)d_in[21];
    const float* mm1 = (const float*)d_in[22];
    const float* vm1 = (const float*)d_in[23];
    const float* Wm2 = (const float*)d_in[24];
    const float* gm2 = (const float*)d_in[25];
    const float* bm2 = (const float*)d_in[26];
    const float* mm2 = (const float*)d_in[27];
    const float* vm2 = (const float*)d_in[28];
    const float* Wm3 = (const float*)d_in[29];
    float* out = (float*)d_out;

    float *x1, *x2, *x3, *off, *e, *sxyz, *kpp, *spart, *S, *fpart, *kpf, *y1, *y2;
    cudaGetSymbolAddress((void**)&x1, g_x1);
    cudaGetSymbolAddress((void**)&x2, g_x2);
    cudaGetSymbolAddress((void**)&x3, g_x3);
    cudaGetSymbolAddress((void**)&off, g_off);
    cudaGetSymbolAddress((void**)&e, g_e);
    cudaGetSymbolAddress((void**)&sxyz, g_sumxyz);
    cudaGetSymbolAddress((void**)&kpp, g_kpp);
    cudaGetSymbolAddress((void**)&spart, g_spart);
    cudaGetSymbolAddress((void**)&S, g_S);
    cudaGetSymbolAddress((void**)&fpart, g_fpart);
    cudaGetSymbolAddress((void**)&kpf, g_kpf);
    cudaGetSymbolAddress((void**)&y1, g_y1);
    cudaGetSymbolAddress((void**)&y2, g_y2);

    // smem: 2 stages x 2(hi,lo) x (128+NT) rows x 12 words x 4B
    constexpr int SM128 = 2 * 2 * (128 + 128) * WSTR * 4;   // 49152 B
    constexpr int SM64  = 2 * 2 * (128 + 64)  * WSTR * 4;   // 36864 B

    cudaFuncSetAttribute(mma_gemm<0, 128>, cudaFuncAttributeMaxDynamicSharedMemorySize, SM128);
    cudaFuncSetAttribute(mma_gemm<1, 64>,  cudaFuncAttributeMaxDynamicSharedMemorySize, SM64);

    // backbone GEMM chain on bf16x3 tensor cores (BN+ReLU / bias fused)
    mma_gemm<0, 128><<<dim3(Mtot / 128, 2), 128, SM128>>>(F,  W1, g1, b1, m1, v1, x1, Mtot, 256, 256);
    mma_gemm<0, 128><<<dim3(Mtot / 128, 2), 128, SM128>>>(x1, W2, g2, b2, m2, v2, x2, Mtot, 256, 256);
    mma_gemm<0, 128><<<dim3(Mtot / 128, 4), 128, SM128>>>(x2, W3, g3, b3, m3, v3, x3, Mtot, 256, 512);
    mma_gemm<1, 64><<<dim3(Mtot / 128, 1), 128, SM64>>>(x3, Wo, bo, nullptr, nullptr, nullptr,
                                                        off, Mtot, 512, 48);
    // keypoint positions (deterministic mean)
    sumxyz_kernel<<<Bc, 256>>>(xyz, sxyz);
    kppos_kernel<<<Bc * Kc, 256>>>(off, sxyz, kpp, out);
    // softmax weights
    expdist_kernel<<<Bc * 64, 256>>>(xyz, off, kpp, e, spart);
    sreduce_kernel<<<1, 128>>>(spart, S);
    // weighted feature pooling
    kpfeat_partial_kernel<<<dim3(16, 4, Bc), 256>>>(F, e, fpart);
    kpfeat_reduce_kernel<<<Bc * Kc, 256>>>(fpart, S, kpf);
    // keypoint MLP (fp32 — tiny, keeps precision headroom)
    mlp_kernel<0><<<dim3(4, Bc), 256>>>(kpf, Wm1, gm1, bm1, mm1, vm1, y1);
    mlp_kernel<0><<<dim3(4, Bc), 256>>>(y1, Wm2, gm2, bm2, mm2, vm2, y2);
    mlp_kernel<1><<<dim3(4, Bc), 256>>>(y2, Wm3, nullptr, nullptr, nullptr, nullptr,
                                        out + Bc * Kc * 3);
}